// round 13
// baseline (speedup 1.0000x reference)
#include <cuda_runtime.h>
#include <cuda_bf16.h>
#include <cuda_fp16.h>
#include <math.h>
#include <stdint.h>

#define Bc 128
#define Sc 64
#define FIN 32
#define Ec 96
#define E2c 192
#define Hc 8
#define Dc 24
#define Lc 4
#define HORc 24
#define FLATc (Sc*E2c)          // 12288
#define ROWS (Bc*Sc)            // 8192
#define MLPH (4*Ec)             // 384

// ---------------- scratch (static device globals; no allocation) ----------
__device__ float g_h0[ROWS*Ec];
__device__ float g_conv[ROWS*E2c];
__device__ float g_h[ROWS*E2c];
__device__ float g_qk[ROWS*E2c];
__device__ float g_v[ROWS*E2c];
__device__ float g_att[ROWS*E2c];
__device__ float g_f[Bc*FLATc];
__device__ __half g_Fh[ROWS*E2c];     // fp16 of current activations (GEMM input)
__device__ __half g_FMh[ROWS*MLPH];   // fp16 mlp hidden
// fc A, fp16, K-tile-major + ldmatrix swizzle:
//   element (m, k): kt=k>>5; c=((k&31)>>3) ^ ((m>>1)&3);
//   half-index = kt*4096 + m*32 + c*8 + (k&7)
__device__ __half g_Ft[Bc*FLATc];

// ---------------- helpers ---------------------------------------------------
__device__ __forceinline__ uint32_t smem_u32(const void* p) {
  uint32_t a;
  asm("{ .reg .u64 t; cvta.to.shared.u64 t, %1; cvt.u32.u64 %0, t; }" : "=r"(a) : "l"(p));
  return a;
}
__device__ __forceinline__ float gelu_f(float x) {
  float t = tanhf(0.7978845608028654f * (x + 0.044715f * x * x * x));
  return 0.5f * x * (1.f + t);
}
__device__ __forceinline__ float softplus_f(float x) {
  return fmaxf(x, 0.f) + log1pf(expf(-fabsf(x)));
}
__device__ __forceinline__ void blk_reduce2(float& a, float& b) {
  __shared__ float ra[256], rb[256];
  int t = threadIdx.x, n = blockDim.x;
  ra[t] = a; rb[t] = b;
  __syncthreads();
  #pragma unroll
  for (int s = 128; s > 0; s >>= 1) {
    if (t < s && t + s < n) { ra[t] += ra[t+s]; rb[t] += rb[t+s]; }
    __syncthreads();
  }
  a = ra[0]; b = rb[0];
}
__device__ __forceinline__ uint32_t pack2h(float a, float b) {
  __half2 h = __floats2half2_rn(a, b);
  return *(uint32_t*)&h;
}
#define MMAH16816(d, a, b) \
  asm volatile("mma.sync.aligned.m16n8k16.row.col.f32.f16.f16.f32 " \
    "{%0,%1,%2,%3}, {%4,%5,%6,%7}, {%8,%9}, {%0,%1,%2,%3};" \
    : "+f"((d)[0]), "+f"((d)[1]), "+f"((d)[2]), "+f"((d)[3]) \
    : "r"((a).x), "r"((a).y), "r"((a).z), "r"((a).w), "r"((b).x), "r"((b).y))
__device__ __forceinline__ void cp16(uint32_t d, const void* s) {
  asm volatile("cp.async.cg.shared.global [%0], [%1], 16;" :: "r"(d), "l"(s));
}
__device__ __forceinline__ void bulkcp(uint32_t d, const void* s, uint32_t n, uint32_t mb) {
  asm volatile("cp.async.bulk.shared::cluster.global.mbarrier::complete_tx::bytes "
               "[%0], [%1], %2, [%3];" :: "r"(d), "l"(s), "r"(n), "r"(mb) : "memory");
}
__device__ __forceinline__ void mbar_wait_acq(uint32_t mb, uint32_t parity) {
  asm volatile(
      "{\n\t.reg .pred P1;\n\t"
      "WAIT_LOOP_%=:\n\t"
      "mbarrier.try_wait.parity.acquire.cta.shared::cta.b64 P1, [%0], %1, 0x989680;\n\t"
      "@P1 bra.uni WAIT_DONE_%=;\n\t"
      "bra.uni WAIT_LOOP_%=;\n\t"
      "WAIT_DONE_%=:\n\t}"
      :: "r"(mb), "r"(parity) : "memory");
}

// ---------------- stage 1: proj -> LN -> gelu -------------------------------
__global__ void k_proj(const float* __restrict__ x, const float* __restrict__ w,
                       const float* __restrict__ bias, const float* __restrict__ ls,
                       const float* __restrict__ lo) {
  int row = blockIdx.x;
  int e = threadIdx.x;
  __shared__ float xs[FIN];
  if (e < FIN) xs[e] = x[row*FIN + e];
  __syncthreads();
  float acc = bias[e];
  #pragma unroll
  for (int k = 0; k < FIN; k++) acc = fmaf(xs[k], w[k*Ec + e], acc);
  float s1 = acc, s2 = acc*acc;
  blk_reduce2(s1, s2);
  float mu = s1 * (1.f/Ec);
  float var = s2 * (1.f/Ec) - mu*mu;
  float y = (acc - mu) * rsqrtf(var + 1e-5f) * ls[e] + lo[e];
  g_h0[row*Ec + e] = gelu_f(y);
}

// ---------------- stage 2: 4x4 SAME conv ------------------------------------
__global__ void k_conv(const float* __restrict__ cw) {
  int i  = blockIdx.y;
  int j0 = blockIdx.x * 16;
  int oc = threadIdx.x;
  __shared__ float sp[4][19*Ec];
  for (int idx = oc; idx < 4*19*Ec; idx += E2c) {
    int di  = idx / (19*Ec);
    int rem = idx - di*19*Ec;
    int col = rem / Ec;
    int c   = rem - col*Ec;
    int gi = i - 1 + di;
    int gj = j0 - 1 + col;
    float v = 0.f;
    if (gi >= 0 && gi < Bc && gj >= 0 && gj < Sc)
      v = g_h0[(gi*Sc + gj)*Ec + c];
    sp[di][col*Ec + c] = v;
  }
  __syncthreads();
  float acc[16];
  #pragma unroll
  for (int j = 0; j < 16; j++) acc[j] = 0.f;
  for (int di = 0; di < 4; di++) {
    for (int c = 0; c < Ec; c++) {
      float pv[19];
      #pragma unroll
      for (int t = 0; t < 19; t++) pv[t] = sp[di][t*Ec + c];
      #pragma unroll
      for (int dj = 0; dj < 4; dj++) {
        float wv = cw[((di*4 + dj)*Ec + c)*E2c + oc];
        #pragma unroll
        for (int j = 0; j < 16; j++) acc[j] = fmaf(pv[j + dj], wv, acc[j]);
      }
    }
  }
  #pragma unroll
  for (int j = 0; j < 16; j++)
    g_conv[(i*Sc + j0 + j)*E2c + oc] = acc[j];
}

// ---------------- stage 3: conv bias -> LN -> gelu (+ fp16 fused) -----------
__global__ void k_ln_gelu_conv(const float* __restrict__ cb,
                               const float* __restrict__ ls, const float* __restrict__ lo) {
  int row = blockIdx.x; int e = threadIdx.x;
  int idx = row*E2c + e;
  float v = g_conv[idx] + cb[e];
  float s1 = v, s2 = v*v;
  blk_reduce2(s1, s2);
  float mu = s1 * (1.f/E2c);
  float var = s2 * (1.f/E2c) - mu*mu;
  float y = gelu_f((v - mu) * rsqrtf(var + 1e-5f) * ls[e] + lo[e]);
  g_h[idx] = y;
  g_Fh[idx] = __float2half_rn(y);
}

// ---------------- tensor-core small GEMM (fp16 single product) ---------------
// mode 0: C = acc+bias   mode 1: FO = fp16(gelu(acc+bias))
// mode 2: C = acc+bias+res, plus fp16 -> g_Ft tiled (N must be E2c)
// blockIdx.z == 1 selects (W2, bias2, C2).
#define GT_APAD 80
#define GT_OFFW 10240           // A fp16 tile 128x80
#define GT_STSZ 18432           // +32x256B fp32 W
#define GT_CV   36864           // after 2 stages
#define GT_WPAD 144
#define GT_SMEM (GT_CV + 32*GT_WPAD)   // 41472

__global__ void __launch_bounds__(256) k_gemm_tc(
    const __half* __restrict__ A,
    const float* W, const float* bias,
    const float* __restrict__ res, float* C,
    __half* __restrict__ FO, __half* __restrict__ Ft,
    const float* W2, const float* bias2, float* C2,
    int N, int K, int mode) {
  extern __shared__ char smc[];
  uint32_t sb = smem_u32(smc);
  int tid = threadIdx.x, lane = tid & 31, wp = tid >> 5;
  int warpM = wp >> 1, warpN = wp & 1;
  int n0 = blockIdx.x * 64, m0 = blockIdx.y * 128;
  int KIT = K >> 5;
  if (blockIdx.z == 1) { W = W2; bias = bias2; C = C2; }

  float acc[2][4][4];
  #pragma unroll
  for (int i = 0; i < 2; i++)
    #pragma unroll
    for (int j = 0; j < 4; j++)
      #pragma unroll
      for (int c = 0; c < 4; c++) acc[i][j][c] = 0.f;

  auto load_stage = [&](int slot, int k0) {
    uint32_t st = sb + slot*GT_STSZ;
    #pragma unroll
    for (int t = 0; t < 2; t++) {
      int g = tid*2 + t;
      int m = g >> 2, c = g & 3;
      cp16(st + m*GT_APAD + c*16, A + (size_t)(m0 + m)*K + k0 + c*8);
    }
    #pragma unroll
    for (int t = 0; t < 2; t++) {
      int g = tid*2 + t;
      int k = g >> 4, c = g & 15;
      cp16(st + GT_OFFW + k*256 + c*16, W + (size_t)(k0 + k)*N + n0 + c*4);
    }
  };

  load_stage(0, 0);
  asm volatile("cp.async.commit_group;" ::: "memory");

  int arow = warpM*32 + (lane & 15);
  int ckrow = tid >> 3, cseg = tid & 7;

  for (int it = 0; it < KIT; it++) {
    asm volatile("cp.async.wait_group 0;" ::: "memory");
    __syncthreads();
    if (it + 1 < KIT) load_stage((it + 1) & 1, (it + 1)*32);
    asm volatile("cp.async.commit_group;" ::: "memory");
    // convert fp32 W tile -> fp16 CV
    {
      uint32_t src = sb + (it & 1)*GT_STSZ + GT_OFFW + (uint32_t)ckrow*256 + cseg*32;
      uint32_t dh  = sb + GT_CV + (uint32_t)ckrow*GT_WPAD + cseg*16;
      float4 f0, f1;
      asm volatile("ld.shared.v4.f32 {%0,%1,%2,%3}, [%4];"
        : "=f"(f0.x), "=f"(f0.y), "=f"(f0.z), "=f"(f0.w) : "r"(src));
      asm volatile("ld.shared.v4.f32 {%0,%1,%2,%3}, [%4];"
        : "=f"(f1.x), "=f"(f1.y), "=f"(f1.z), "=f"(f1.w) : "r"(src + 16));
      uint32_t h0 = pack2h(f0.x, f0.y), h1 = pack2h(f0.z, f0.w);
      uint32_t h2 = pack2h(f1.x, f1.y), h3 = pack2h(f1.z, f1.w);
      asm volatile("st.shared.v4.b32 [%0], {%1,%2,%3,%4};"
        :: "r"(dh), "r"(h0), "r"(h1), "r"(h2), "r"(h3));
    }
    __syncthreads();
    uint32_t st = sb + (it & 1)*GT_STSZ;
    uint32_t cv = sb + GT_CV;
    #pragma unroll
    for (int ks = 0; ks < 2; ks++) {
      uint4 fah[2];
      int c = ks*2 + (lane >> 4);
      #pragma unroll
      for (int i = 0; i < 2; i++) {
        uint32_t ad = st + (uint32_t)(arow + i*16)*GT_APAD + c*16;
        asm volatile("ldmatrix.sync.aligned.m8n8.x4.shared.b16 {%0,%1,%2,%3}, [%4];"
          : "=r"(fah[i].x), "=r"(fah[i].y), "=r"(fah[i].z), "=r"(fah[i].w) : "r"(ad));
      }
      uint2 fwh[4];
      int kl = ks*16 + (lane & 15);
      #pragma unroll
      for (int j = 0; j < 4; j++) {
        uint32_t wd = cv + (uint32_t)kl*GT_WPAD + (uint32_t)(warpN*32 + j*8)*2;
        asm volatile("ldmatrix.sync.aligned.m8n8.x2.trans.shared.b16 {%0,%1}, [%2];"
          : "=r"(fwh[j].x), "=r"(fwh[j].y) : "r"(wd));
      }
      #pragma unroll
      for (int i = 0; i < 2; i++)
        #pragma unroll
        for (int j = 0; j < 4; j++) MMAH16816(acc[i][j], fah[i], fwh[j]);
    }
  }

  int g = lane >> 2, q = lane & 3;
  #pragma unroll
  for (int i = 0; i < 2; i++) {
    int m = m0 + warpM*32 + i*16 + g;
    #pragma unroll
    for (int j = 0; j < 4; j++) {
      int n = n0 + warpN*32 + j*8 + q*2;
      float b0 = bias[n], b1 = bias[n+1];
      float v00 = acc[i][j][0] + b0, v01 = acc[i][j][1] + b1;
      float v10 = acc[i][j][2] + b0, v11 = acc[i][j][3] + b1;
      if (mode == 1) {
        *(uint32_t*)(FO + (size_t)m*N + n)     = pack2h(gelu_f(v00), gelu_f(v01));
        *(uint32_t*)(FO + (size_t)(m+8)*N + n) = pack2h(gelu_f(v10), gelu_f(v11));
      } else {
        if (mode == 2) {
          float2 r0 = *(const float2*)(res + (size_t)m*N + n);
          float2 r1 = *(const float2*)(res + (size_t)(m+8)*N + n);
          v00 += r0.x; v01 += r0.y; v10 += r1.x; v11 += r1.y;
          // g_Ft tiled store (N == E2c): fc k = (m%64)*E2c + n
          #pragma unroll
          for (int rr = 0; rr < 2; rr++) {
            int mm = m + rr*8;
            int bb = mm >> 6, ss = mm & 63;
            int kt = ss*6 + (n >> 5);
            int cc = ((n & 31) >> 3) ^ ((bb >> 1) & 3);
            size_t hoff = (size_t)kt*4096 + bb*32 + cc*8 + (n & 7);
            *(uint32_t*)(Ft + hoff) = rr ? pack2h(v10, v11) : pack2h(v00, v01);
          }
        }
        *(float2*)(C + (size_t)m*N + n)     = make_float2(v00, v01);
        *(float2*)(C + (size_t)(m+8)*N + n) = make_float2(v10, v11);
      }
    }
  }
}

// ---------------- gravity attention core (mass fused) ------------------------
__global__ void k_attn(const float* __restrict__ mw, const float* __restrict__ mb) {
  int bh = blockIdx.x; int b = bh >> 3, hh = bh & 7;
  int i = threadIdx.x;
  __shared__ float qs[Sc][Dc+1];
  __shared__ float vs[Sc][Dc+1];
  __shared__ float ms[Sc];
  __shared__ float sq[Sc];
  const float* qbase = g_qk + (size_t)(b*Sc)*E2c + hh*Dc;
  const float* vbase = g_v  + (size_t)(b*Sc)*E2c + hh*Dc;
  float qi[Dc];
  float ssq = 0.f;
  #pragma unroll
  for (int d = 0; d < Dc; d++) {
    float q = qbase[i*E2c + d];
    qs[i][d] = q; qi[d] = q; ssq = fmaf(q, q, ssq);
    vs[i][d] = vbase[i*E2c + d];
  }
  sq[i] = ssq;
  // mass for this row (inline, was k_mass)
  {
    const float* hrow = g_h + (size_t)(b*Sc + i)*E2c;
    float mcc = mb[hh];
    #pragma unroll 4
    for (int k = 0; k < E2c; k++) mcc = fmaf(hrow[k], mw[k*Hc + hh], mcc);
    ms[i] = softplus_f(mcc);
  }
  __syncthreads();
  float mi = ms[i];
  float mmax = -INFINITY, l = 0.f;
  float acc[Dc];
  #pragma unroll
  for (int d = 0; d < Dc; d++) acc[d] = 0.f;
  for (int j = 0; j < Sc; j++) {
    float dot = 0.f;
    #pragma unroll
    for (int d = 0; d < Dc; d++) dot = fmaf(qi[d], qs[j][d], dot);
    float d2 = fmaxf(ssq + sq[j] - 2.f*dot, 0.f) + 1e-6f;
    float sc = mi * ms[j] / d2;
    float mn = fmaxf(mmax, sc);
    float scale = __expf(mmax - mn);
    float p = __expf(sc - mn);
    l = l*scale + p;
    #pragma unroll
    for (int d = 0; d < Dc; d++) acc[d] = fmaf(p, vs[j][d], acc[d]*scale);
    mmax = mn;
  }
  float inv = 1.f / l;
  float* obase = g_att + (size_t)(b*Sc + i)*E2c + hh*Dc;
  #pragma unroll
  for (int d = 0; d < Dc; d++) obase[d] = acc[d] * inv;
}

// ---------------- residual + LN + gelu (+ fp16 fused) ------------------------
__global__ void k_res_ln_gelu(const float* __restrict__ ls, const float* __restrict__ lo) {
  int row = blockIdx.x; int e = threadIdx.x;
  int idx = row*E2c + e;
  float v = g_h[idx] + g_att[idx];
  float s1 = v, s2 = v*v;
  blk_reduce2(s1, s2);
  float mu = s1 * (1.f/E2c);
  float var = s2 * (1.f/E2c) - mu*mu;
  float y = gelu_f((v - mu) * rsqrtf(var + 1e-5f) * ls[e] + lo[e]);
  g_h[idx] = y;
  g_Fh[idx] = __float2half_rn(y);
}

// ---------------- fc GEMM: A via single bulk-copy, W via cp.async ------------
// D[128, 48-slab]; grid=256, 2 CTAs/SM, 4-stage hybrid pipeline.
#define FC_BN 48
#define FC_IT (FLATc/32)        // 384
#define FC_ST 4
#define FC_ABYTES 8192          // A tile: 128 rows x 64B (swizzled, contiguous)
#define FC_WBYTES 6144          // W tile: 32 rows x 192B fp32
#define FST_SZ (FC_ABYTES + FC_WBYTES)   // 14336
#define FMB_OFF 0               // 4 mbarriers
#define FSTG_OFF 64
#define FCV_OFF (FSTG_OFF + FC_ST*FST_SZ)  // 57408
#define FW_PAD 112
#define FC_SMEM (FCV_OFF + 32*FW_PAD)      // 60992

__global__ void __launch_bounds__(256, 2) k_fc_mma(const float* __restrict__ W,
                                                   const float* __restrict__ bias) {
  extern __shared__ char smc[];
  uint32_t sb = smem_u32(smc);
  int tid = threadIdx.x, lane = tid & 31, wp = tid >> 5;
  int warpM = wp >> 1, warpN = wp & 1;
  int n0 = blockIdx.x * FC_BN;

  float acc[2][3][4];
  #pragma unroll
  for (int i = 0; i < 2; i++)
    #pragma unroll
    for (int j = 0; j < 3; j++)
      #pragma unroll
      for (int c = 0; c < 4; c++) acc[i][j][c] = 0.f;

  if (tid == 0) {
    #pragma unroll
    for (int s = 0; s < FC_ST; s++)
      asm volatile("mbarrier.init.shared.b64 [%0], 1;" :: "r"(sb + FMB_OFF + s*8) : "memory");
  }
  __syncthreads();

  auto issue_W = [&](int slot, int kit) {
    uint32_t st = sb + FSTG_OFF + slot*FST_SZ + FC_ABYTES;
    {
      int k = tid / 12, c = tid % 12;
      cp16(st + k*192 + c*16, W + (size_t)(kit*32 + k)*FLATc + n0 + c*4);
    }
    if (tid < 128) {
      int g2 = tid + 256;
      int k = g2 / 12, c = g2 % 12;
      cp16(st + k*192 + c*16, W + (size_t)(kit*32 + k)*FLATc + n0 + c*4);
    }
  };
  auto issue_A = [&](int slot, int kit) {
    uint32_t st = sb + FSTG_OFF + slot*FST_SZ;
    uint32_t mb = sb + FMB_OFF + slot*8;
    if (lane == 0) {
      asm volatile("mbarrier.arrive.expect_tx.shared.b64 _, [%0], %1;"
                   :: "r"(mb), "r"((uint32_t)FC_ABYTES) : "memory");
      bulkcp(st, (const char*)g_Ft + (size_t)kit*FC_ABYTES, FC_ABYTES, mb);
    }
  };

  #pragma unroll
  for (int s = 0; s < FC_ST - 1; s++) {
    issue_W(s, s);
    asm volatile("cp.async.commit_group;" ::: "memory");
    if (wp == 0) issue_A(s, s);
  }

  uint32_t phbits = 0;
  int arow = warpM*32 + (lane & 15);
  int ckrow = tid >> 3, cseg = tid & 7;

  for (int it = 0; it < FC_IT; it++) {
    int slot = it & 3;
    asm volatile("cp.async.wait_group 2;" ::: "memory");
    mbar_wait_acq(sb + FMB_OFF + slot*8, (phbits >> slot) & 1);
    phbits ^= 1u << slot;
    __syncthreads();

    if (it + FC_ST - 1 < FC_IT) issue_W((it + FC_ST - 1) & 3, it + FC_ST - 1);
    asm volatile("cp.async.commit_group;" ::: "memory");
    if (wp == 0 && it + FC_ST - 1 < FC_IT) issue_A((it + FC_ST - 1) & 3, it + FC_ST - 1);

    // convert fp32 W tile (slot) -> fp16 CV
    {
      uint32_t src = sb + FSTG_OFF + slot*FST_SZ + FC_ABYTES + (uint32_t)ckrow*192 + cseg*24;
      uint32_t dh  = sb + FCV_OFF + (uint32_t)ckrow*FW_PAD + cseg*12;
      float2 f0, f1, f2;
      asm volatile("ld.shared.v2.f32 {%0,%1}, [%2];" : "=f"(f0.x), "=f"(f0.y) : "r"(src));
      asm volatile("ld.shared.v2.f32 {%0,%1}, [%2];" : "=f"(f1.x), "=f"(f1.y) : "r"(src + 8));
      asm volatile("ld.shared.v2.f32 {%0,%1}, [%2];" : "=f"(f2.x), "=f"(f2.y) : "r"(src + 16));
      uint32_t h0 = pack2h(f0.x, f0.y), h1 = pack2h(f1.x, f1.y), h2 = pack2h(f2.x, f2.y);
      asm volatile("st.shared.b32 [%0], %1;" :: "r"(dh),     "r"(h0));
      asm volatile("st.shared.b32 [%0], %1;" :: "r"(dh + 4), "r"(h1));
      asm volatile("st.shared.b32 [%0], %1;" :: "r"(dh + 8), "r"(h2));
    }
    __syncthreads();

    uint32_t st = sb + FSTG_OFF + slot*FST_SZ;
    uint32_t cv = sb + FCV_OFF;
    #pragma unroll
    for (int ks = 0; ks < 2; ks++) {
      uint4 fah[2];
      int c = ks*2 + (lane >> 4);
      #pragma unroll
      for (int i = 0; i < 2; i++) {
        int row = arow + i*16;
        uint32_t sw = (uint32_t)((c ^ ((row >> 1) & 3)) * 16);
        uint32_t ad = st + (uint32_t)row*64 + sw;
        asm volatile("ldmatrix.sync.aligned.m8n8.x4.shared.b16 {%0,%1,%2,%3}, [%4];"
          : "=r"(fah[i].x), "=r"(fah[i].y), "=r"(fah[i].z), "=r"(fah[i].w) : "r"(ad));
      }
      uint2 fwh[3];
      int kl = ks*16 + (lane & 15);
      #pragma unroll
      for (int j = 0; j < 3; j++) {
        uint32_t wd = cv + (uint32_t)kl*FW_PAD + (uint32_t)(warpN*24 + j*8)*2;
        asm volatile("ldmatrix.sync.aligned.m8n8.x2.trans.shared.b16 {%0,%1}, [%2];"
          : "=r"(fwh[j].x), "=r"(fwh[j].y) : "r"(wd));
      }
      #pragma unroll
      for (int i = 0; i < 2; i++)
        #pragma unroll
        for (int j = 0; j < 3; j++) MMAH16816(acc[i][j], fah[i], fwh[j]);
    }
  }

  // epilogue: bias + gelu -> g_f
  int g = lane >> 2, q = lane & 3;
  #pragma unroll
  for (int i = 0; i < 2; i++) {
    int m = warpM*32 + i*16 + g;
    #pragma unroll
    for (int j = 0; j < 3; j++) {
      int n = n0 + warpN*24 + j*8 + q*2;
      float b0 = bias[n], b1 = bias[n+1];
      float2 r0, r1;
      r0.x = gelu_f(acc[i][j][0] + b0);
      r0.y = gelu_f(acc[i][j][1] + b1);
      r1.x = gelu_f(acc[i][j][2] + b0);
      r1.y = gelu_f(acc[i][j][3] + b1);
      *(float2*)(g_f + (size_t)m*FLATc + n)       = r0;
      *(float2*)(g_f + (size_t)(m + 8)*FLATc + n) = r1;
    }
  }
}

// ---------------- LN over FLAT -----------------------------------------------
__global__ void k_ln_flat(const float* __restrict__ ls, const float* __restrict__ lo) {
  int b = blockIdx.x; int t = threadIdx.x;
  float* frow = g_f + (size_t)b*FLATc;
  float s1 = 0.f, s2 = 0.f;
  for (int k = t; k < FLATc; k += 256) { float v = frow[k]; s1 += v; s2 += v*v; }
  blk_reduce2(s1, s2);
  float mu = s1 * (1.f/FLATc);
  float var = s2 * (1.f/FLATc) - mu*mu;
  float rs = rsqrtf(var + 1e-5f);
  for (int k = t; k < FLATc; k += 256) {
    float v = frow[k];
    frow[k] = (v - mu) * rs * ls[k] + lo[k];
  }
}

// ---------------- final out GEMM ---------------------------------------------
__global__ void k_out(const float* __restrict__ ow, const float* __restrict__ ob,
                      float* __restrict__ out) {
  int o = blockIdx.x, b = blockIdx.y;
  int t = threadIdx.x;
  const float* frow = g_f + (size_t)b*FLATc;
  float s1 = 0.f, s2 = 0.f;
  for (int k = t; k < FLATc; k += 256) s1 = fmaf(frow[k], ow[(size_t)k*HORc + o], s1);
  blk_reduce2(s1, s2);
  if (t == 0) out[b*HORc + o] = s1 + ob[o];
}

// ---------------- launch ------------------------------------------------------
extern "C" void kernel_launch(void* const* d_in, const int* in_sizes, int n_in,
                              void* d_out, int out_size) {
  const float* x      = (const float*)d_in[0];
  const float* proj_w = (const float*)d_in[1];
  const float* proj_b = (const float*)d_in[2];
  const float* ln0_s  = (const float*)d_in[3];
  const float* ln0_o  = (const float*)d_in[4];
  const float* conv_w = (const float*)d_in[5];
  const float* conv_b = (const float*)d_in[6];
  const float* ln1_s  = (const float*)d_in[7];
  const float* ln1_o  = (const float*)d_in[8];
  const float* qk_w   = (const float*)d_in[9];
  const float* qk_b   = (const float*)d_in[10];
  const float* mass_w = (const float*)d_in[11];
  const float* mass_b = (const float*)d_in[12];
  const float* v_w    = (const float*)d_in[13];
  const float* v_b    = (const float*)d_in[14];
  const float* norm_s = (const float*)d_in[15];
  const float* norm_o = (const float*)d_in[16];
  const float* mlp_w1 = (const float*)d_in[17];
  const float* mlp_b1 = (const float*)d_in[18];
  const float* mlp_w2 = (const float*)d_in[19];
  const float* mlp_b2 = (const float*)d_in[20];
  const float* fc_w   = (const float*)d_in[21];
  const float* fc_b   = (const float*)d_in[22];
  const float* ln2_s  = (const float*)d_in[23];
  const float* ln2_o  = (const float*)d_in[24];
  const float* out_w  = (const float*)d_in[25];
  const float* out_b  = (const float*)d_in[26];

  float *p_h, *p_qk, *p_v;
  __half *p_Fh, *p_FMh, *p_Ft;
  cudaGetSymbolAddress((void**)&p_h,   g_h);
  cudaGetSymbolAddress((void**)&p_qk,  g_qk);
  cudaGetSymbolAddress((void**)&p_v,   g_v);
  cudaGetSymbolAddress((void**)&p_Fh,  g_Fh);
  cudaGetSymbolAddress((void**)&p_FMh, g_FMh);
  cudaGetSymbolAddress((void**)&p_Ft,  g_Ft);

  cudaFuncSetAttribute(k_fc_mma, cudaFuncAttributeMaxDynamicSharedMemorySize, FC_SMEM);
  cudaFuncSetAttribute(k_gemm_tc, cudaFuncAttributeMaxDynamicSharedMemorySize, GT_SMEM);

  k_proj<<<ROWS, Ec>>>(x, proj_w, proj_b, ln0_s, ln0_o);
  k_conv<<<dim3(4, Bc), E2c>>>(conv_w);
  k_ln_gelu_conv<<<ROWS, E2c>>>(conv_b, ln1_s, ln1_o);

  for (int l = 0; l < Lc; l++) {
    // merged qk + v GEMMs: z=0 -> qk, z=1 -> v
    k_gemm_tc<<<dim3(E2c/64, ROWS/128, 2), 256, GT_SMEM>>>(
        p_Fh, qk_w + (size_t)l*E2c*E2c, qk_b + l*E2c,
        nullptr, p_qk, nullptr, nullptr,
        v_w + (size_t)l*E2c*E2c, v_b + l*E2c, p_v,
        E2c, E2c, 0);
    k_attn<<<Bc*Hc, Sc>>>(mass_w + (size_t)l*E2c*Hc, mass_b + l*Hc);
    k_res_ln_gelu<<<ROWS, E2c>>>(norm_s + l*E2c, norm_o + l*E2c);
  }

  // MLP: w1 (gelu -> fp16), w2 (+residual, + tiled fp16 for fc)
  k_gemm_tc<<<dim3(MLPH/64, ROWS/128, 1), 256, GT_SMEM>>>(
      p_Fh, mlp_w1, mlp_b1, nullptr, nullptr, p_FMh, nullptr,
      nullptr, nullptr, nullptr, MLPH, E2c, 1);
  k_gemm_tc<<<dim3(E2c/64, ROWS/128, 1), 256, GT_SMEM>>>(
      p_FMh, mlp_w2, mlp_b2, p_h, p_h, nullptr, p_Ft,
      nullptr, nullptr, nullptr, E2c, MLPH, 2);

  k_fc_mma<<<FLATc/FC_BN, 256, FC_SMEM>>>(fc_w, fc_b);
  k_ln_flat<<<Bc, 256>>>(ln2_s, ln2_o);
  k_out<<<dim3(HORc, Bc), 256>>>(out_w, out_b, (float*)d_out);
}

// round 14
// speedup vs baseline: 1.1488x; 1.1488x over previous
#include <cuda_runtime.h>
#include <cuda_bf16.h>
#include <cuda_fp16.h>
#include <math.h>
#include <stdint.h>

#define Bc 128
#define Sc 64
#define FIN 32
#define Ec 96
#define E2c 192
#define Hc 8
#define Dc 24
#define Lc 4
#define HORc 24
#define FLATc (Sc*E2c)          // 12288
#define ROWS (Bc*Sc)            // 8192
#define MLPH (4*Ec)             // 384

// ---------------- scratch (static device globals; no allocation) ----------
__device__ float g_h0[ROWS*Ec];
__device__ float g_conv[ROWS*E2c];
__device__ float g_h[ROWS*E2c];
__device__ float g_qk[ROWS*E2c];
__device__ float g_v[ROWS*E2c];
__device__ float g_mass[Bc*Hc*Sc];
__device__ float g_att[ROWS*E2c];
__device__ float g_f[Bc*FLATc];
__device__ __half g_Fh[ROWS*E2c];     // fp16 of current activations (GEMM input)
__device__ __half g_FMh[ROWS*MLPH];   // fp16 mlp hidden
// fc A, fp16, K-tile-major + ldmatrix swizzle:
//   element (m, k): kt=k>>5; c=((k&31)>>3) ^ ((m>>1)&3);
//   half-index = kt*4096 + m*32 + c*8 + (k&7)
__device__ __half g_Ft[Bc*FLATc];

// ---------------- helpers ---------------------------------------------------
__device__ __forceinline__ uint32_t smem_u32(const void* p) {
  uint32_t a;
  asm("{ .reg .u64 t; cvta.to.shared.u64 t, %1; cvt.u32.u64 %0, t; }" : "=r"(a) : "l"(p));
  return a;
}
__device__ __forceinline__ float gelu_f(float x) {
  float t = tanhf(0.7978845608028654f * (x + 0.044715f * x * x * x));
  return 0.5f * x * (1.f + t);
}
__device__ __forceinline__ float softplus_f(float x) {
  return fmaxf(x, 0.f) + log1pf(expf(-fabsf(x)));
}
__device__ __forceinline__ void blk_reduce2(float& a, float& b) {
  __shared__ float ra[256], rb[256];
  int t = threadIdx.x, n = blockDim.x;
  ra[t] = a; rb[t] = b;
  __syncthreads();
  #pragma unroll
  for (int s = 128; s > 0; s >>= 1) {
    if (t < s && t + s < n) { ra[t] += ra[t+s]; rb[t] += rb[t+s]; }
    __syncthreads();
  }
  a = ra[0]; b = rb[0];
}
__device__ __forceinline__ uint32_t pack2h(float a, float b) {
  __half2 h = __floats2half2_rn(a, b);
  return *(uint32_t*)&h;
}
#define MMAH16816(d, a, b) \
  asm volatile("mma.sync.aligned.m16n8k16.row.col.f32.f16.f16.f32 " \
    "{%0,%1,%2,%3}, {%4,%5,%6,%7}, {%8,%9}, {%0,%1,%2,%3};" \
    : "+f"((d)[0]), "+f"((d)[1]), "+f"((d)[2]), "+f"((d)[3]) \
    : "r"((a).x), "r"((a).y), "r"((a).z), "r"((a).w), "r"((b).x), "r"((b).y))
__device__ __forceinline__ void cp16(uint32_t d, const void* s) {
  asm volatile("cp.async.cg.shared.global [%0], [%1], 16;" :: "r"(d), "l"(s));
}
__device__ __forceinline__ void bulkcp(uint32_t d, const void* s, uint32_t n, uint32_t mb) {
  asm volatile("cp.async.bulk.shared::cluster.global.mbarrier::complete_tx::bytes "
               "[%0], [%1], %2, [%3];" :: "r"(d), "l"(s), "r"(n), "r"(mb) : "memory");
}
__device__ __forceinline__ void mbar_wait_acq(uint32_t mb, uint32_t parity) {
  asm volatile(
      "{\n\t.reg .pred P1;\n\t"
      "WAIT_LOOP_%=:\n\t"
      "mbarrier.try_wait.parity.acquire.cta.shared::cta.b64 P1, [%0], %1, 0x989680;\n\t"
      "@P1 bra.uni WAIT_DONE_%=;\n\t"
      "bra.uni WAIT_LOOP_%=;\n\t"
      "WAIT_DONE_%=:\n\t}"
      :: "r"(mb), "r"(parity) : "memory");
}

// ---------------- stage 1: proj -> LN -> gelu -------------------------------
__global__ void k_proj(const float* __restrict__ x, const float* __restrict__ w,
                       const float* __restrict__ bias, const float* __restrict__ ls,
                       const float* __restrict__ lo) {
  int row = blockIdx.x;
  int e = threadIdx.x;
  __shared__ float xs[FIN];
  if (e < FIN) xs[e] = x[row*FIN + e];
  __syncthreads();
  float acc = bias[e];
  #pragma unroll
  for (int k = 0; k < FIN; k++) acc = fmaf(xs[k], w[k*Ec + e], acc);
  float s1 = acc, s2 = acc*acc;
  blk_reduce2(s1, s2);
  float mu = s1 * (1.f/Ec);
  float var = s2 * (1.f/Ec) - mu*mu;
  float y = (acc - mu) * rsqrtf(var + 1e-5f) * ls[e] + lo[e];
  g_h0[row*Ec + e] = gelu_f(y);
}

// ---------------- stage 2: 4x4 SAME conv ------------------------------------
__global__ void k_conv(const float* __restrict__ cw) {
  int i  = blockIdx.y;
  int j0 = blockIdx.x * 16;
  int oc = threadIdx.x;
  __shared__ float sp[4][19*Ec];
  for (int idx = oc; idx < 4*19*Ec; idx += E2c) {
    int di  = idx / (19*Ec);
    int rem = idx - di*19*Ec;
    int col = rem / Ec;
    int c   = rem - col*Ec;
    int gi = i - 1 + di;
    int gj = j0 - 1 + col;
    float v = 0.f;
    if (gi >= 0 && gi < Bc && gj >= 0 && gj < Sc)
      v = g_h0[(gi*Sc + gj)*Ec + c];
    sp[di][col*Ec + c] = v;
  }
  __syncthreads();
  float acc[16];
  #pragma unroll
  for (int j = 0; j < 16; j++) acc[j] = 0.f;
  for (int di = 0; di < 4; di++) {
    for (int c = 0; c < Ec; c++) {
      float pv[19];
      #pragma unroll
      for (int t = 0; t < 19; t++) pv[t] = sp[di][t*Ec + c];
      #pragma unroll
      for (int dj = 0; dj < 4; dj++) {
        float wv = cw[((di*4 + dj)*Ec + c)*E2c + oc];
        #pragma unroll
        for (int j = 0; j < 16; j++) acc[j] = fmaf(pv[j + dj], wv, acc[j]);
      }
    }
  }
  #pragma unroll
  for (int j = 0; j < 16; j++)
    g_conv[(i*Sc + j0 + j)*E2c + oc] = acc[j];
}

// ---------------- stage 3: conv bias -> LN -> gelu (+ fp16 fused) -----------
__global__ void k_ln_gelu_conv(const float* __restrict__ cb,
                               const float* __restrict__ ls, const float* __restrict__ lo) {
  int row = blockIdx.x; int e = threadIdx.x;
  int idx = row*E2c + e;
  float v = g_conv[idx] + cb[e];
  float s1 = v, s2 = v*v;
  blk_reduce2(s1, s2);
  float mu = s1 * (1.f/E2c);
  float var = s2 * (1.f/E2c) - mu*mu;
  float y = gelu_f((v - mu) * rsqrtf(var + 1e-5f) * ls[e] + lo[e]);
  g_h[idx] = y;
  g_Fh[idx] = __float2half_rn(y);
}

// ---------------- tensor-core small GEMM (fp16 single product) ---------------
// mode 0: C = acc+bias   mode 1: FO = fp16(gelu(acc+bias))
// mode 2: C = acc+bias+res, plus fp16 -> g_Ft tiled (N must be E2c)
// blockIdx.z == 1 selects (W2, bias2, C2).
#define GT_APAD 80
#define GT_OFFW 10240           // A fp16 tile 128x80
#define GT_STSZ 18432           // +32x256B fp32 W
#define GT_CV   36864           // after 2 stages
#define GT_WPAD 144
#define GT_SMEM (GT_CV + 32*GT_WPAD)   // 41472

__global__ void __launch_bounds__(256) k_gemm_tc(
    const __half* __restrict__ A,
    const float* W, const float* bias,
    const float* __restrict__ res, float* C,
    __half* __restrict__ FO, __half* __restrict__ Ft,
    const float* W2, const float* bias2, float* C2,
    int N, int K, int mode) {
  extern __shared__ char smc[];
  uint32_t sb = smem_u32(smc);
  int tid = threadIdx.x, lane = tid & 31, wp = tid >> 5;
  int warpM = wp >> 1, warpN = wp & 1;
  int n0 = blockIdx.x * 64, m0 = blockIdx.y * 128;
  int KIT = K >> 5;
  if (blockIdx.z == 1) { W = W2; bias = bias2; C = C2; }

  float acc[2][4][4];
  #pragma unroll
  for (int i = 0; i < 2; i++)
    #pragma unroll
    for (int j = 0; j < 4; j++)
      #pragma unroll
      for (int c = 0; c < 4; c++) acc[i][j][c] = 0.f;

  auto load_stage = [&](int slot, int k0) {
    uint32_t st = sb + slot*GT_STSZ;
    #pragma unroll
    for (int t = 0; t < 2; t++) {
      int g = tid*2 + t;
      int m = g >> 2, c = g & 3;
      cp16(st + m*GT_APAD + c*16, A + (size_t)(m0 + m)*K + k0 + c*8);
    }
    #pragma unroll
    for (int t = 0; t < 2; t++) {
      int g = tid*2 + t;
      int k = g >> 4, c = g & 15;
      cp16(st + GT_OFFW + k*256 + c*16, W + (size_t)(k0 + k)*N + n0 + c*4);
    }
  };

  load_stage(0, 0);
  asm volatile("cp.async.commit_group;" ::: "memory");

  int arow = warpM*32 + (lane & 15);
  int ckrow = tid >> 3, cseg = tid & 7;

  for (int it = 0; it < KIT; it++) {
    asm volatile("cp.async.wait_group 0;" ::: "memory");
    __syncthreads();
    if (it + 1 < KIT) load_stage((it + 1) & 1, (it + 1)*32);
    asm volatile("cp.async.commit_group;" ::: "memory");
    // convert fp32 W tile -> fp16 CV
    {
      uint32_t src = sb + (it & 1)*GT_STSZ + GT_OFFW + (uint32_t)ckrow*256 + cseg*32;
      uint32_t dh  = sb + GT_CV + (uint32_t)ckrow*GT_WPAD + cseg*16;
      float4 f0, f1;
      asm volatile("ld.shared.v4.f32 {%0,%1,%2,%3}, [%4];"
        : "=f"(f0.x), "=f"(f0.y), "=f"(f0.z), "=f"(f0.w) : "r"(src));
      asm volatile("ld.shared.v4.f32 {%0,%1,%2,%3}, [%4];"
        : "=f"(f1.x), "=f"(f1.y), "=f"(f1.z), "=f"(f1.w) : "r"(src + 16));
      uint32_t h0 = pack2h(f0.x, f0.y), h1 = pack2h(f0.z, f0.w);
      uint32_t h2 = pack2h(f1.x, f1.y), h3 = pack2h(f1.z, f1.w);
      asm volatile("st.shared.v4.b32 [%0], {%1,%2,%3,%4};"
        :: "r"(dh), "r"(h0), "r"(h1), "r"(h2), "r"(h3));
    }
    __syncthreads();
    uint32_t st = sb + (it & 1)*GT_STSZ;
    uint32_t cv = sb + GT_CV;
    #pragma unroll
    for (int ks = 0; ks < 2; ks++) {
      uint4 fah[2];
      int c = ks*2 + (lane >> 4);
      #pragma unroll
      for (int i = 0; i < 2; i++) {
        uint32_t ad = st + (uint32_t)(arow + i*16)*GT_APAD + c*16;
        asm volatile("ldmatrix.sync.aligned.m8n8.x4.shared.b16 {%0,%1,%2,%3}, [%4];"
          : "=r"(fah[i].x), "=r"(fah[i].y), "=r"(fah[i].z), "=r"(fah[i].w) : "r"(ad));
      }
      uint2 fwh[4];
      int kl = ks*16 + (lane & 15);
      #pragma unroll
      for (int j = 0; j < 4; j++) {
        uint32_t wd = cv + (uint32_t)kl*GT_WPAD + (uint32_t)(warpN*32 + j*8)*2;
        asm volatile("ldmatrix.sync.aligned.m8n8.x2.trans.shared.b16 {%0,%1}, [%2];"
          : "=r"(fwh[j].x), "=r"(fwh[j].y) : "r"(wd));
      }
      #pragma unroll
      for (int i = 0; i < 2; i++)
        #pragma unroll
        for (int j = 0; j < 4; j++) MMAH16816(acc[i][j], fah[i], fwh[j]);
    }
  }

  int g = lane >> 2, q = lane & 3;
  #pragma unroll
  for (int i = 0; i < 2; i++) {
    int m = m0 + warpM*32 + i*16 + g;
    #pragma unroll
    for (int j = 0; j < 4; j++) {
      int n = n0 + warpN*32 + j*8 + q*2;
      float b0 = bias[n], b1 = bias[n+1];
      float v00 = acc[i][j][0] + b0, v01 = acc[i][j][1] + b1;
      float v10 = acc[i][j][2] + b0, v11 = acc[i][j][3] + b1;
      if (mode == 1) {
        *(uint32_t*)(FO + (size_t)m*N + n)     = pack2h(gelu_f(v00), gelu_f(v01));
        *(uint32_t*)(FO + (size_t)(m+8)*N + n) = pack2h(gelu_f(v10), gelu_f(v11));
      } else {
        if (mode == 2) {
          float2 r0 = *(const float2*)(res + (size_t)m*N + n);
          float2 r1 = *(const float2*)(res + (size_t)(m+8)*N + n);
          v00 += r0.x; v01 += r0.y; v10 += r1.x; v11 += r1.y;
          // g_Ft tiled store (N == E2c): fc k = (m%64)*E2c + n
          #pragma unroll
          for (int rr = 0; rr < 2; rr++) {
            int mm = m + rr*8;
            int bb = mm >> 6, ss = mm & 63;
            int kt = ss*6 + (n >> 5);
            int cc = ((n & 31) >> 3) ^ ((bb >> 1) & 3);
            size_t hoff = (size_t)kt*4096 + bb*32 + cc*8 + (n & 7);
            *(uint32_t*)(Ft + hoff) = rr ? pack2h(v10, v11) : pack2h(v00, v01);
          }
        }
        *(float2*)(C + (size_t)m*N + n)     = make_float2(v00, v01);
        *(float2*)(C + (size_t)(m+8)*N + n) = make_float2(v10, v11);
      }
    }
  }
}

// ---------------- mass head (coalesced shared staging) -----------------------
__global__ void k_mass(const float* __restrict__ mw, const float* __restrict__ mb) {
  __shared__ float hs[32][E2c+1];
  __shared__ float ws[E2c*Hc];
  int r0 = blockIdx.x * 32;
  int tid = threadIdx.x;
  for (int idx = tid; idx < 32*E2c; idx += 256) {
    int r = idx / E2c, k = idx - (idx / E2c)*E2c;
    hs[r][k] = g_h[(r0 + r)*E2c + k];
  }
  for (int idx = tid; idx < E2c*Hc; idx += 256) ws[idx] = mw[idx];
  __syncthreads();
  int r = tid >> 3, hh = tid & 7;
  float acc = mb[hh];
  #pragma unroll 4
  for (int k = 0; k < E2c; k++) acc = fmaf(hs[r][k], ws[k*Hc + hh], acc);
  int row = r0 + r; int b = row >> 6, s = row & 63;
  g_mass[(b*Hc + hh)*Sc + s] = softplus_f(acc);
}

// ---------------- gravity attention core -------------------------------------
__global__ void k_attn() {
  int bh = blockIdx.x; int b = bh >> 3, hh = bh & 7;
  int i = threadIdx.x;
  __shared__ float qs[Sc][Dc+1];
  __shared__ float vs[Sc][Dc+1];
  __shared__ float ms[Sc];
  __shared__ float sq[Sc];
  const float* qbase = g_qk + (size_t)(b*Sc)*E2c + hh*Dc;
  const float* vbase = g_v  + (size_t)(b*Sc)*E2c + hh*Dc;
  float qi[Dc];
  float ssq = 0.f;
  #pragma unroll
  for (int d = 0; d < Dc; d++) {
    float q = qbase[i*E2c + d];
    qs[i][d] = q; qi[d] = q; ssq = fmaf(q, q, ssq);
    vs[i][d] = vbase[i*E2c + d];
  }
  sq[i] = ssq;
  ms[i] = g_mass[(b*Hc + hh)*Sc + i];
  __syncthreads();
  float mi = ms[i];
  float mmax = -INFINITY, l = 0.f;
  float acc[Dc];
  #pragma unroll
  for (int d = 0; d < Dc; d++) acc[d] = 0.f;
  for (int j = 0; j < Sc; j++) {
    float dot = 0.f;
    #pragma unroll
    for (int d = 0; d < Dc; d++) dot = fmaf(qi[d], qs[j][d], dot);
    float d2 = fmaxf(ssq + sq[j] - 2.f*dot, 0.f) + 1e-6f;
    float sc = mi * ms[j] / d2;
    float mn = fmaxf(mmax, sc);
    float scale = __expf(mmax - mn);
    float p = __expf(sc - mn);
    l = l*scale + p;
    #pragma unroll
    for (int d = 0; d < Dc; d++) acc[d] = fmaf(p, vs[j][d], acc[d]*scale);
    mmax = mn;
  }
  float inv = 1.f / l;
  float* obase = g_att + (size_t)(b*Sc + i)*E2c + hh*Dc;
  #pragma unroll
  for (int d = 0; d < Dc; d++) obase[d] = acc[d] * inv;
}

// ---------------- residual + LN + gelu (+ fp16 fused) ------------------------
__global__ void k_res_ln_gelu(const float* __restrict__ ls, const float* __restrict__ lo) {
  int row = blockIdx.x; int e = threadIdx.x;
  int idx = row*E2c + e;
  float v = g_h[idx] + g_att[idx];
  float s1 = v, s2 = v*v;
  blk_reduce2(s1, s2);
  float mu = s1 * (1.f/E2c);
  float var = s2 * (1.f/E2c) - mu*mu;
  float y = gelu_f((v - mu) * rsqrtf(var + 1e-5f) * ls[e] + lo[e]);
  g_h[idx] = y;
  g_Fh[idx] = __float2half_rn(y);
}

// ---------------- fc GEMM: A via single bulk-copy, W via cp.async ------------
// D[128, 48-slab]; grid=256, 2 CTAs/SM, 4-stage hybrid pipeline.
#define FC_BN 48
#define FC_IT (FLATc/32)        // 384
#define FC_ST 4
#define FC_ABYTES 8192          // A tile: 128 rows x 64B (swizzled, contiguous)
#define FC_WBYTES 6144          // W tile: 32 rows x 192B fp32
#define FST_SZ (FC_ABYTES + FC_WBYTES)   // 14336
#define FMB_OFF 0               // 4 mbarriers
#define FSTG_OFF 64
#define FCV_OFF (FSTG_OFF + FC_ST*FST_SZ)  // 57408
#define FW_PAD 112
#define FC_SMEM (FCV_OFF + 32*FW_PAD)      // 60992

__global__ void __launch_bounds__(256, 2) k_fc_mma(const float* __restrict__ W,
                                                   const float* __restrict__ bias) {
  extern __shared__ char smc[];
  uint32_t sb = smem_u32(smc);
  int tid = threadIdx.x, lane = tid & 31, wp = tid >> 5;
  int warpM = wp >> 1, warpN = wp & 1;
  int n0 = blockIdx.x * FC_BN;

  float acc[2][3][4];
  #pragma unroll
  for (int i = 0; i < 2; i++)
    #pragma unroll
    for (int j = 0; j < 3; j++)
      #pragma unroll
      for (int c = 0; c < 4; c++) acc[i][j][c] = 0.f;

  if (tid == 0) {
    #pragma unroll
    for (int s = 0; s < FC_ST; s++)
      asm volatile("mbarrier.init.shared.b64 [%0], 1;" :: "r"(sb + FMB_OFF + s*8) : "memory");
  }
  __syncthreads();

  auto issue_W = [&](int slot, int kit) {
    uint32_t st = sb + FSTG_OFF + slot*FST_SZ + FC_ABYTES;
    {
      int k = tid / 12, c = tid % 12;
      cp16(st + k*192 + c*16, W + (size_t)(kit*32 + k)*FLATc + n0 + c*4);
    }
    if (tid < 128) {
      int g2 = tid + 256;
      int k = g2 / 12, c = g2 % 12;
      cp16(st + k*192 + c*16, W + (size_t)(kit*32 + k)*FLATc + n0 + c*4);
    }
  };
  auto issue_A = [&](int slot, int kit) {
    uint32_t st = sb + FSTG_OFF + slot*FST_SZ;
    uint32_t mb = sb + FMB_OFF + slot*8;
    if (lane == 0) {
      asm volatile("mbarrier.arrive.expect_tx.shared.b64 _, [%0], %1;"
                   :: "r"(mb), "r"((uint32_t)FC_ABYTES) : "memory");
      bulkcp(st, (const char*)g_Ft + (size_t)kit*FC_ABYTES, FC_ABYTES, mb);
    }
  };

  #pragma unroll
  for (int s = 0; s < FC_ST - 1; s++) {
    issue_W(s, s);
    asm volatile("cp.async.commit_group;" ::: "memory");
    if (wp == 0) issue_A(s, s);
  }

  uint32_t phbits = 0;
  int arow = warpM*32 + (lane & 15);
  int ckrow = tid >> 3, cseg = tid & 7;

  for (int it = 0; it < FC_IT; it++) {
    int slot = it & 3;
    asm volatile("cp.async.wait_group 2;" ::: "memory");
    mbar_wait_acq(sb + FMB_OFF + slot*8, (phbits >> slot) & 1);
    phbits ^= 1u << slot;
    __syncthreads();

    if (it + FC_ST - 1 < FC_IT) issue_W((it + FC_ST - 1) & 3, it + FC_ST - 1);
    asm volatile("cp.async.commit_group;" ::: "memory");
    if (wp == 0 && it + FC_ST - 1 < FC_IT) issue_A((it + FC_ST - 1) & 3, it + FC_ST - 1);

    // convert fp32 W tile (slot) -> fp16 CV
    {
      uint32_t src = sb + FSTG_OFF + slot*FST_SZ + FC_ABYTES + (uint32_t)ckrow*192 + cseg*24;
      uint32_t dh  = sb + FCV_OFF + (uint32_t)ckrow*FW_PAD + cseg*12;
      float2 f0, f1, f2;
      asm volatile("ld.shared.v2.f32 {%0,%1}, [%2];" : "=f"(f0.x), "=f"(f0.y) : "r"(src));
      asm volatile("ld.shared.v2.f32 {%0,%1}, [%2];" : "=f"(f1.x), "=f"(f1.y) : "r"(src + 8));
      asm volatile("ld.shared.v2.f32 {%0,%1}, [%2];" : "=f"(f2.x), "=f"(f2.y) : "r"(src + 16));
      uint32_t h0 = pack2h(f0.x, f0.y), h1 = pack2h(f1.x, f1.y), h2 = pack2h(f2.x, f2.y);
      asm volatile("st.shared.b32 [%0], %1;" :: "r"(dh),     "r"(h0));
      asm volatile("st.shared.b32 [%0], %1;" :: "r"(dh + 4), "r"(h1));
      asm volatile("st.shared.b32 [%0], %1;" :: "r"(dh + 8), "r"(h2));
    }
    __syncthreads();

    uint32_t st = sb + FSTG_OFF + slot*FST_SZ;
    uint32_t cv = sb + FCV_OFF;
    #pragma unroll
    for (int ks = 0; ks < 2; ks++) {
      uint4 fah[2];
      int c = ks*2 + (lane >> 4);
      #pragma unroll
      for (int i = 0; i < 2; i++) {
        int row = arow + i*16;
        uint32_t sw = (uint32_t)((c ^ ((row >> 1) & 3)) * 16);
        uint32_t ad = st + (uint32_t)row*64 + sw;
        asm volatile("ldmatrix.sync.aligned.m8n8.x4.shared.b16 {%0,%1,%2,%3}, [%4];"
          : "=r"(fah[i].x), "=r"(fah[i].y), "=r"(fah[i].z), "=r"(fah[i].w) : "r"(ad));
      }
      uint2 fwh[3];
      int kl = ks*16 + (lane & 15);
      #pragma unroll
      for (int j = 0; j < 3; j++) {
        uint32_t wd = cv + (uint32_t)kl*FW_PAD + (uint32_t)(warpN*24 + j*8)*2;
        asm volatile("ldmatrix.sync.aligned.m8n8.x2.trans.shared.b16 {%0,%1}, [%2];"
          : "=r"(fwh[j].x), "=r"(fwh[j].y) : "r"(wd));
      }
      #pragma unroll
      for (int i = 0; i < 2; i++)
        #pragma unroll
        for (int j = 0; j < 3; j++) MMAH16816(acc[i][j], fah[i], fwh[j]);
    }
  }

  // epilogue: bias + gelu -> g_f
  int g = lane >> 2, q = lane & 3;
  #pragma unroll
  for (int i = 0; i < 2; i++) {
    int m = warpM*32 + i*16 + g;
    #pragma unroll
    for (int j = 0; j < 3; j++) {
      int n = n0 + warpN*24 + j*8 + q*2;
      float b0 = bias[n], b1 = bias[n+1];
      float2 r0, r1;
      r0.x = gelu_f(acc[i][j][0] + b0);
      r0.y = gelu_f(acc[i][j][1] + b1);
      r1.x = gelu_f(acc[i][j][2] + b0);
      r1.y = gelu_f(acc[i][j][3] + b1);
      *(float2*)(g_f + (size_t)m*FLATc + n)       = r0;
      *(float2*)(g_f + (size_t)(m + 8)*FLATc + n) = r1;
    }
  }
}

// ---------------- LN over FLAT -----------------------------------------------
__global__ void k_ln_flat(const float* __restrict__ ls, const float* __restrict__ lo) {
  int b = blockIdx.x; int t = threadIdx.x;
  float* frow = g_f + (size_t)b*FLATc;
  float s1 = 0.f, s2 = 0.f;
  for (int k = t; k < FLATc; k += 256) { float v = frow[k]; s1 += v; s2 += v*v; }
  blk_reduce2(s1, s2);
  float mu = s1 * (1.f/FLATc);
  float var = s2 * (1.f/FLATc) - mu*mu;
  float rs = rsqrtf(var + 1e-5f);
  for (int k = t; k < FLATc; k += 256) {
    float v = frow[k];
    frow[k] = (v - mu) * rs * ls[k] + lo[k];
  }
}

// ---------------- final out GEMM ---------------------------------------------
__global__ void k_out(const float* __restrict__ ow, const float* __restrict__ ob,
                      float* __restrict__ out) {
  int o = blockIdx.x, b = blockIdx.y;
  int t = threadIdx.x;
  const float* frow = g_f + (size_t)b*FLATc;
  float s1 = 0.f, s2 = 0.f;
  for (int k = t; k < FLATc; k += 256) s1 = fmaf(frow[k], ow[(size_t)k*HORc + o], s1);
  blk_reduce2(s1, s2);
  if (t == 0) out[b*HORc + o] = s1 + ob[o];
}

// ---------------- launch ------------------------------------------------------
extern "C" void kernel_launch(void* const* d_in, const int* in_sizes, int n_in,
                              void* d_out, int out_size) {
  const float* x      = (const float*)d_in[0];
  const float* proj_w = (const float*)d_in[1];
  const float* proj_b = (const float*)d_in[2];
  const float* ln0_s  = (const float*)d_in[3];
  const float* ln0_o  = (const float*)d_in[4];
  const float* conv_w = (const float*)d_in[5];
  const float* conv_b = (const float*)d_in[6];
  const float* ln1_s  = (const float*)d_in[7];
  const float* ln1_o  = (const float*)d_in[8];
  const float* qk_w   = (const float*)d_in[9];
  const float* qk_b   = (const float*)d_in[10];
  const float* mass_w = (const float*)d_in[11];
  const float* mass_b = (const float*)d_in[12];
  const float* v_w    = (const float*)d_in[13];
  const float* v_b    = (const float*)d_in[14];
  const float* norm_s = (const float*)d_in[15];
  const float* norm_o = (const float*)d_in[16];
  const float* mlp_w1 = (const float*)d_in[17];
  const float* mlp_b1 = (const float*)d_in[18];
  const float* mlp_w2 = (const float*)d_in[19];
  const float* mlp_b2 = (const float*)d_in[20];
  const float* fc_w   = (const float*)d_in[21];
  const float* fc_b   = (const float*)d_in[22];
  const float* ln2_s  = (const float*)d_in[23];
  const float* ln2_o  = (const float*)d_in[24];
  const float* out_w  = (const float*)d_in[25];
  const float* out_b  = (const float*)d_in[26];

  float *p_h, *p_qk, *p_v;
  __half *p_Fh, *p_FMh, *p_Ft;
  cudaGetSymbolAddress((void**)&p_h,   g_h);
  cudaGetSymbolAddress((void**)&p_qk,  g_qk);
  cudaGetSymbolAddress((void**)&p_v,   g_v);
  cudaGetSymbolAddress((void**)&p_Fh,  g_Fh);
  cudaGetSymbolAddress((void**)&p_FMh, g_FMh);
  cudaGetSymbolAddress((void**)&p_Ft,  g_Ft);

  cudaFuncSetAttribute(k_fc_mma, cudaFuncAttributeMaxDynamicSharedMemorySize, FC_SMEM);
  cudaFuncSetAttribute(k_gemm_tc, cudaFuncAttributeMaxDynamicSharedMemorySize, GT_SMEM);

  k_proj<<<ROWS, Ec>>>(x, proj_w, proj_b, ln0_s, ln0_o);
  k_conv<<<dim3(4, Bc), E2c>>>(conv_w);
  k_ln_gelu_conv<<<ROWS, E2c>>>(conv_b, ln1_s, ln1_o);

  for (int l = 0; l < Lc; l++) {
    // merged qk + v GEMMs: z=0 -> qk, z=1 -> v
    k_gemm_tc<<<dim3(E2c/64, ROWS/128, 2), 256, GT_SMEM>>>(
        p_Fh, qk_w + (size_t)l*E2c*E2c, qk_b + l*E2c,
        nullptr, p_qk, nullptr, nullptr,
        v_w + (size_t)l*E2c*E2c, v_b + l*E2c, p_v,
        E2c, E2c, 0);
    k_mass<<<ROWS/32, 256>>>(mass_w + (size_t)l*E2c*Hc, mass_b + l*Hc);
    k_attn<<<Bc*Hc, Sc>>>();
    k_res_ln_gelu<<<ROWS, E2c>>>(norm_s + l*E2c, norm_o + l*E2c);
  }

  // MLP: w1 (gelu -> fp16), w2 (+residual, + tiled fp16 for fc)
  k_gemm_tc<<<dim3(MLPH/64, ROWS/128, 1), 256, GT_SMEM>>>(
      p_Fh, mlp_w1, mlp_b1, nullptr, nullptr, p_FMh, nullptr,
      nullptr, nullptr, nullptr, MLPH, E2c, 1);
  k_gemm_tc<<<dim3(E2c/64, ROWS/128, 1), 256, GT_SMEM>>>(
      p_FMh, mlp_w2, mlp_b2, p_h, p_h, nullptr, p_Ft,
      nullptr, nullptr, nullptr, E2c, MLPH, 2);

  k_fc_mma<<<FLATc/FC_BN, 256, FC_SMEM>>>(fc_w, fc_b);
  k_ln_flat<<<Bc, 256>>>(ln2_s, ln2_o);
  k_out<<<dim3(HORc, Bc), 256>>>(out_w, out_b, (float*)d_out);
}

// round 15
// speedup vs baseline: 1.4234x; 1.2390x over previous
#include <cuda_runtime.h>
#include <cuda_bf16.h>
#include <cuda_fp16.h>
#include <math.h>
#include <stdint.h>

#define Bc 128
#define Sc 64
#define FIN 32
#define Ec 96
#define E2c 192
#define Hc 8
#define Dc 24
#define Lc 4
#define HORc 24
#define FLATc (Sc*E2c)          // 12288
#define ROWS (Bc*Sc)            // 8192
#define MLPH (4*Ec)             // 384

// ---------------- scratch (static device globals; no allocation) ----------
__device__ float g_conv[ROWS*E2c];
__device__ float g_h[ROWS*E2c];
__device__ float g_qk[ROWS*E2c];
__device__ float g_v[ROWS*E2c];
__device__ float g_mass[Bc*Hc*Sc];
__device__ float g_att[ROWS*E2c];
__device__ float g_f[Bc*FLATc];
__device__ __half g_F0[ROWS*Ec];      // fp16 image after proj (conv input)
__device__ __half g_Fh[ROWS*E2c];     // fp16 of current activations (GEMM input)
__device__ __half g_FMh[ROWS*MLPH];   // fp16 mlp hidden
__device__ float g_zero[64];          // zero page (OOB conv reads; never written)
// fc A, fp16, K-tile-major + ldmatrix swizzle:
//   element (m, k): kt=k>>5; c=((k&31)>>3) ^ ((m>>1)&3);
//   half-index = kt*4096 + m*32 + c*8 + (k&7)
__device__ __half g_Ft[Bc*FLATc];

// ---------------- helpers ---------------------------------------------------
__device__ __forceinline__ uint32_t smem_u32(const void* p) {
  uint32_t a;
  asm("{ .reg .u64 t; cvta.to.shared.u64 t, %1; cvt.u32.u64 %0, t; }" : "=r"(a) : "l"(p));
  return a;
}
__device__ __forceinline__ float gelu_f(float x) {
  float t = tanhf(0.7978845608028654f * (x + 0.044715f * x * x * x));
  return 0.5f * x * (1.f + t);
}
__device__ __forceinline__ float softplus_f(float x) {
  return fmaxf(x, 0.f) + log1pf(expf(-fabsf(x)));
}
__device__ __forceinline__ void blk_reduce2(float& a, float& b) {
  __shared__ float ra[256], rb[256];
  int t = threadIdx.x, n = blockDim.x;
  ra[t] = a; rb[t] = b;
  __syncthreads();
  #pragma unroll
  for (int s = 128; s > 0; s >>= 1) {
    if (t < s && t + s < n) { ra[t] += ra[t+s]; rb[t] += rb[t+s]; }
    __syncthreads();
  }
  a = ra[0]; b = rb[0];
}
__device__ __forceinline__ uint32_t pack2h(float a, float b) {
  __half2 h = __floats2half2_rn(a, b);
  return *(uint32_t*)&h;
}
#define MMAH16816(d, a, b) \
  asm volatile("mma.sync.aligned.m16n8k16.row.col.f32.f16.f16.f32 " \
    "{%0,%1,%2,%3}, {%4,%5,%6,%7}, {%8,%9}, {%0,%1,%2,%3};" \
    : "+f"((d)[0]), "+f"((d)[1]), "+f"((d)[2]), "+f"((d)[3]) \
    : "r"((a).x), "r"((a).y), "r"((a).z), "r"((a).w), "r"((b).x), "r"((b).y))
__device__ __forceinline__ void cp16(uint32_t d, const void* s) {
  asm volatile("cp.async.cg.shared.global [%0], [%1], 16;" :: "r"(d), "l"(s));
}
__device__ __forceinline__ void bulkcp(uint32_t d, const void* s, uint32_t n, uint32_t mb) {
  asm volatile("cp.async.bulk.shared::cluster.global.mbarrier::complete_tx::bytes "
               "[%0], [%1], %2, [%3];" :: "r"(d), "l"(s), "r"(n), "r"(mb) : "memory");
}
__device__ __forceinline__ void mbar_wait_acq(uint32_t mb, uint32_t parity) {
  asm volatile(
      "{\n\t.reg .pred P1;\n\t"
      "WAIT_LOOP_%=:\n\t"
      "mbarrier.try_wait.parity.acquire.cta.shared::cta.b64 P1, [%0], %1, 0x989680;\n\t"
      "@P1 bra.uni WAIT_DONE_%=;\n\t"
      "bra.uni WAIT_LOOP_%=;\n\t"
      "WAIT_DONE_%=:\n\t}"
      :: "r"(mb), "r"(parity) : "memory");
}

// ---------------- stage 1: proj -> LN -> gelu (fp16 out) ---------------------
__global__ void k_proj(const float* __restrict__ x, const float* __restrict__ w,
                       const float* __restrict__ bias, const float* __restrict__ ls,
                       const float* __restrict__ lo) {
  int row = blockIdx.x;
  int e = threadIdx.x;
  __shared__ float xs[FIN];
  if (e < FIN) xs[e] = x[row*FIN + e];
  __syncthreads();
  float acc = bias[e];
  #pragma unroll
  for (int k = 0; k < FIN; k++) acc = fmaf(xs[k], w[k*Ec + e], acc);
  float s1 = acc, s2 = acc*acc;
  blk_reduce2(s1, s2);
  float mu = s1 * (1.f/Ec);
  float var = s2 * (1.f/Ec) - mu*mu;
  float y = (acc - mu) * rsqrtf(var + 1e-5f) * ls[e] + lo[e];
  g_F0[row*Ec + e] = __float2half_rn(gelu_f(y));
}

// ---------------- tensor-core small GEMM (fp16 single product) ---------------
// mode 0: C = acc+bias   mode 1: FO = fp16(gelu(acc+bias))
// mode 2: C = acc+bias+res, plus fp16 -> g_Ft tiled (N must be E2c)
// blockIdx.z == 1 selects (W2, bias2, C2).
#define GT_APAD 80
#define GT_OFFW 10240           // A fp16 tile 128x80
#define GT_STSZ 18432           // +32x256B fp32 W
#define GT_CV   36864           // after 2 stages
#define GT_WPAD 144
#define GT_SMEM (GT_CV + 32*GT_WPAD)   // 41472

__global__ void __launch_bounds__(256) k_gemm_tc(
    const __half* __restrict__ A,
    const float* W, const float* bias,
    const float* __restrict__ res, float* C,
    __half* __restrict__ FO, __half* __restrict__ Ft,
    const float* W2, const float* bias2, float* C2,
    int N, int K, int mode) {
  extern __shared__ char smc[];
  uint32_t sb = smem_u32(smc);
  int tid = threadIdx.x, lane = tid & 31, wp = tid >> 5;
  int warpM = wp >> 1, warpN = wp & 1;
  int n0 = blockIdx.x * 64, m0 = blockIdx.y * 128;
  int KIT = K >> 5;
  if (blockIdx.z == 1) { W = W2; bias = bias2; C = C2; }

  float acc[2][4][4];
  #pragma unroll
  for (int i = 0; i < 2; i++)
    #pragma unroll
    for (int j = 0; j < 4; j++)
      #pragma unroll
      for (int c = 0; c < 4; c++) acc[i][j][c] = 0.f;

  auto load_stage = [&](int slot, int k0) {
    uint32_t st = sb + slot*GT_STSZ;
    #pragma unroll
    for (int t = 0; t < 2; t++) {
      int g = tid*2 + t;
      int m = g >> 2, c = g & 3;
      cp16(st + m*GT_APAD + c*16, A + (size_t)(m0 + m)*K + k0 + c*8);
    }
    #pragma unroll
    for (int t = 0; t < 2; t++) {
      int g = tid*2 + t;
      int k = g >> 4, c = g & 15;
      cp16(st + GT_OFFW + k*256 + c*16, W + (size_t)(k0 + k)*N + n0 + c*4);
    }
  };

  load_stage(0, 0);
  asm volatile("cp.async.commit_group;" ::: "memory");

  int arow = warpM*32 + (lane & 15);
  int ckrow = tid >> 3, cseg = tid & 7;

  for (int it = 0; it < KIT; it++) {
    asm volatile("cp.async.wait_group 0;" ::: "memory");
    __syncthreads();
    if (it + 1 < KIT) load_stage((it + 1) & 1, (it + 1)*32);
    asm volatile("cp.async.commit_group;" ::: "memory");
    {
      uint32_t src = sb + (it & 1)*GT_STSZ + GT_OFFW + (uint32_t)ckrow*256 + cseg*32;
      uint32_t dh  = sb + GT_CV + (uint32_t)ckrow*GT_WPAD + cseg*16;
      float4 f0, f1;
      asm volatile("ld.shared.v4.f32 {%0,%1,%2,%3}, [%4];"
        : "=f"(f0.x), "=f"(f0.y), "=f"(f0.z), "=f"(f0.w) : "r"(src));
      asm volatile("ld.shared.v4.f32 {%0,%1,%2,%3}, [%4];"
        : "=f"(f1.x), "=f"(f1.y), "=f"(f1.z), "=f"(f1.w) : "r"(src + 16));
      uint32_t h0 = pack2h(f0.x, f0.y), h1 = pack2h(f0.z, f0.w);
      uint32_t h2 = pack2h(f1.x, f1.y), h3 = pack2h(f1.z, f1.w);
      asm volatile("st.shared.v4.b32 [%0], {%1,%2,%3,%4};"
        :: "r"(dh), "r"(h0), "r"(h1), "r"(h2), "r"(h3));
    }
    __syncthreads();
    uint32_t st = sb + (it & 1)*GT_STSZ;
    uint32_t cv = sb + GT_CV;
    #pragma unroll
    for (int ks = 0; ks < 2; ks++) {
      uint4 fah[2];
      int c = ks*2 + (lane >> 4);
      #pragma unroll
      for (int i = 0; i < 2; i++) {
        uint32_t ad = st + (uint32_t)(arow + i*16)*GT_APAD + c*16;
        asm volatile("ldmatrix.sync.aligned.m8n8.x4.shared.b16 {%0,%1,%2,%3}, [%4];"
          : "=r"(fah[i].x), "=r"(fah[i].y), "=r"(fah[i].z), "=r"(fah[i].w) : "r"(ad));
      }
      uint2 fwh[4];
      int kl = ks*16 + (lane & 15);
      #pragma unroll
      for (int j = 0; j < 4; j++) {
        uint32_t wd = cv + (uint32_t)kl*GT_WPAD + (uint32_t)(warpN*32 + j*8)*2;
        asm volatile("ldmatrix.sync.aligned.m8n8.x2.trans.shared.b16 {%0,%1}, [%2];"
          : "=r"(fwh[j].x), "=r"(fwh[j].y) : "r"(wd));
      }
      #pragma unroll
      for (int i = 0; i < 2; i++)
        #pragma unroll
        for (int j = 0; j < 4; j++) MMAH16816(acc[i][j], fah[i], fwh[j]);
    }
  }

  int g = lane >> 2, q = lane & 3;
  #pragma unroll
  for (int i = 0; i < 2; i++) {
    int m = m0 + warpM*32 + i*16 + g;
    #pragma unroll
    for (int j = 0; j < 4; j++) {
      int n = n0 + warpN*32 + j*8 + q*2;
      float b0 = bias[n], b1 = bias[n+1];
      float v00 = acc[i][j][0] + b0, v01 = acc[i][j][1] + b1;
      float v10 = acc[i][j][2] + b0, v11 = acc[i][j][3] + b1;
      if (mode == 1) {
        *(uint32_t*)(FO + (size_t)m*N + n)     = pack2h(gelu_f(v00), gelu_f(v01));
        *(uint32_t*)(FO + (size_t)(m+8)*N + n) = pack2h(gelu_f(v10), gelu_f(v11));
      } else {
        if (mode == 2) {
          float2 r0 = *(const float2*)(res + (size_t)m*N + n);
          float2 r1 = *(const float2*)(res + (size_t)(m+8)*N + n);
          v00 += r0.x; v01 += r0.y; v10 += r1.x; v11 += r1.y;
          #pragma unroll
          for (int rr = 0; rr < 2; rr++) {
            int mm = m + rr*8;
            int bb = mm >> 6, ss = mm & 63;
            int kt = ss*6 + (n >> 5);
            int cc = ((n & 31) >> 3) ^ ((bb >> 1) & 3);
            size_t hoff = (size_t)kt*4096 + bb*32 + cc*8 + (n & 7);
            *(uint32_t*)(Ft + hoff) = rr ? pack2h(v10, v11) : pack2h(v00, v01);
          }
        }
        *(float2*)(C + (size_t)m*N + n)     = make_float2(v00, v01);
        *(float2*)(C + (size_t)(m+8)*N + n) = make_float2(v10, v11);
      }
    }
  }
}

// ---------------- conv as implicit GEMM (fp16) -------------------------------
// out[p, oc] = sum_{di,dj,c} F0[pix(p,di,dj), c] * cw[((di*4+dj)*96+c)*192+oc]
// K = 1536 (48 chunks of 32; each chunk = fixed (di,dj), 32 contiguous channels)
__global__ void __launch_bounds__(256) k_conv_tc(
    const __half* __restrict__ F0, const float* __restrict__ W,
    const float* __restrict__ bias, float* __restrict__ C) {
  extern __shared__ char smc[];
  uint32_t sb = smem_u32(smc);
  int tid = threadIdx.x, lane = tid & 31, wp = tid >> 5;
  int warpM = wp >> 1, warpN = wp & 1;
  int n0 = blockIdx.x * 64, m0 = blockIdx.y * 128;

  float acc[2][4][4];
  #pragma unroll
  for (int i = 0; i < 2; i++)
    #pragma unroll
    for (int j = 0; j < 4; j++)
      #pragma unroll
      for (int c = 0; c < 4; c++) acc[i][j][c] = 0.f;

  auto load_stage = [&](int slot, int kt) {
    uint32_t st = sb + slot*GT_STSZ;
    int di = kt / 12, rem = kt - di*12;
    int dj = rem / 3, c0 = (rem - dj*3) * 32;
    #pragma unroll
    for (int t = 0; t < 2; t++) {
      int g = tid*2 + t;
      int m = g >> 2, c = g & 3;
      int p = m0 + m, ii = p >> 6, jj = p & 63;
      int gi = ii + di - 1, gj = jj + dj - 1;
      const void* src;
      if (gi >= 0 && gi < Bc && gj >= 0 && gj < Sc)
        src = F0 + (size_t)(gi*Sc + gj)*Ec + c0 + c*8;
      else
        src = g_zero;
      cp16(st + m*GT_APAD + c*16, src);
    }
    #pragma unroll
    for (int t = 0; t < 2; t++) {
      int g = tid*2 + t;
      int k = g >> 4, c = g & 15;
      cp16(st + GT_OFFW + k*256 + c*16, W + (size_t)(kt*32 + k)*E2c + n0 + c*4);
    }
  };

  load_stage(0, 0);
  asm volatile("cp.async.commit_group;" ::: "memory");

  int arow = warpM*32 + (lane & 15);
  int ckrow = tid >> 3, cseg = tid & 7;

  for (int it = 0; it < 48; it++) {
    asm volatile("cp.async.wait_group 0;" ::: "memory");
    __syncthreads();
    if (it + 1 < 48) load_stage((it + 1) & 1, it + 1);
    asm volatile("cp.async.commit_group;" ::: "memory");
    {
      uint32_t src = sb + (it & 1)*GT_STSZ + GT_OFFW + (uint32_t)ckrow*256 + cseg*32;
      uint32_t dh  = sb + GT_CV + (uint32_t)ckrow*GT_WPAD + cseg*16;
      float4 f0, f1;
      asm volatile("ld.shared.v4.f32 {%0,%1,%2,%3}, [%4];"
        : "=f"(f0.x), "=f"(f0.y), "=f"(f0.z), "=f"(f0.w) : "r"(src));
      asm volatile("ld.shared.v4.f32 {%0,%1,%2,%3}, [%4];"
        : "=f"(f1.x), "=f"(f1.y), "=f"(f1.z), "=f"(f1.w) : "r"(src + 16));
      uint32_t h0 = pack2h(f0.x, f0.y), h1 = pack2h(f0.z, f0.w);
      uint32_t h2 = pack2h(f1.x, f1.y), h3 = pack2h(f1.z, f1.w);
      asm volatile("st.shared.v4.b32 [%0], {%1,%2,%3,%4};"
        :: "r"(dh), "r"(h0), "r"(h1), "r"(h2), "r"(h3));
    }
    __syncthreads();
    uint32_t st = sb + (it & 1)*GT_STSZ;
    uint32_t cv = sb + GT_CV;
    #pragma unroll
    for (int ks = 0; ks < 2; ks++) {
      uint4 fah[2];
      int c = ks*2 + (lane >> 4);
      #pragma unroll
      for (int i = 0; i < 2; i++) {
        uint32_t ad = st + (uint32_t)(arow + i*16)*GT_APAD + c*16;
        asm volatile("ldmatrix.sync.aligned.m8n8.x4.shared.b16 {%0,%1,%2,%3}, [%4];"
          : "=r"(fah[i].x), "=r"(fah[i].y), "=r"(fah[i].z), "=r"(fah[i].w) : "r"(ad));
      }
      uint2 fwh[4];
      int kl = ks*16 + (lane & 15);
      #pragma unroll
      for (int j = 0; j < 4; j++) {
        uint32_t wd = cv + (uint32_t)kl*GT_WPAD + (uint32_t)(warpN*32 + j*8)*2;
        asm volatile("ldmatrix.sync.aligned.m8n8.x2.trans.shared.b16 {%0,%1}, [%2];"
          : "=r"(fwh[j].x), "=r"(fwh[j].y) : "r"(wd));
      }
      #pragma unroll
      for (int i = 0; i < 2; i++)
        #pragma unroll
        for (int j = 0; j < 4; j++) MMAH16816(acc[i][j], fah[i], fwh[j]);
    }
  }

  int g = lane >> 2, q = lane & 3;
  #pragma unroll
  for (int i = 0; i < 2; i++) {
    int m = m0 + warpM*32 + i*16 + g;
    #pragma unroll
    for (int j = 0; j < 4; j++) {
      int n = n0 + warpN*32 + j*8 + q*2;
      float b0 = bias[n], b1 = bias[n+1];
      *(float2*)(C + (size_t)m*E2c + n)     = make_float2(acc[i][j][0] + b0, acc[i][j][1] + b1);
      *(float2*)(C + (size_t)(m+8)*E2c + n) = make_float2(acc[i][j][2] + b0, acc[i][j][3] + b1);
    }
  }
}

// ---------------- stage 3: LN -> gelu (+ fp16 fused; bias already in conv) ---
__global__ void k_ln_gelu_conv(const float* __restrict__ ls, const float* __restrict__ lo) {
  int row = blockIdx.x; int e = threadIdx.x;
  int idx = row*E2c + e;
  float v = g_conv[idx];
  float s1 = v, s2 = v*v;
  blk_reduce2(s1, s2);
  float mu = s1 * (1.f/E2c);
  float var = s2 * (1.f/E2c) - mu*mu;
  float y = gelu_f((v - mu) * rsqrtf(var + 1e-5f) * ls[e] + lo[e]);
  g_h[idx] = y;
  g_Fh[idx] = __float2half_rn(y);
}

// ---------------- mass head (coalesced shared staging) -----------------------
__global__ void k_mass(const float* __restrict__ mw, const float* __restrict__ mb) {
  __shared__ float hs[32][E2c+1];
  __shared__ float ws[E2c*Hc];
  int r0 = blockIdx.x * 32;
  int tid = threadIdx.x;
  for (int idx = tid; idx < 32*E2c; idx += 256) {
    int r = idx / E2c, k = idx - (idx / E2c)*E2c;
    hs[r][k] = g_h[(r0 + r)*E2c + k];
  }
  for (int idx = tid; idx < E2c*Hc; idx += 256) ws[idx] = mw[idx];
  __syncthreads();
  int r = tid >> 3, hh = tid & 7;
  float acc = mb[hh];
  #pragma unroll 4
  for (int k = 0; k < E2c; k++) acc = fmaf(hs[r][k], ws[k*Hc + hh], acc);
  int row = r0 + r; int b = row >> 6, s = row & 63;
  g_mass[(b*Hc + hh)*Sc + s] = softplus_f(acc);
}

// ---------------- gravity attention core -------------------------------------
__global__ void k_attn() {
  int bh = blockIdx.x; int b = bh >> 3, hh = bh & 7;
  int i = threadIdx.x;
  __shared__ float qs[Sc][Dc+1];
  __shared__ float vs[Sc][Dc+1];
  __shared__ float ms[Sc];
  __shared__ float sq[Sc];
  const float* qbase = g_qk + (size_t)(b*Sc)*E2c + hh*Dc;
  const float* vbase = g_v  + (size_t)(b*Sc)*E2c + hh*Dc;
  float qi[Dc];
  float ssq = 0.f;
  #pragma unroll
  for (int d = 0; d < Dc; d++) {
    float q = qbase[i*E2c + d];
    qs[i][d] = q; qi[d] = q; ssq = fmaf(q, q, ssq);
    vs[i][d] = vbase[i*E2c + d];
  }
  sq[i] = ssq;
  ms[i] = g_mass[(b*Hc + hh)*Sc + i];
  __syncthreads();
  float mi = ms[i];
  float mmax = -INFINITY, l = 0.f;
  float acc[Dc];
  #pragma unroll
  for (int d = 0; d < Dc; d++) acc[d] = 0.f;
  for (int j = 0; j < Sc; j++) {
    float dot = 0.f;
    #pragma unroll
    for (int d = 0; d < Dc; d++) dot = fmaf(qi[d], qs[j][d], dot);
    float d2 = fmaxf(ssq + sq[j] - 2.f*dot, 0.f) + 1e-6f;
    float sc = mi * ms[j] / d2;
    float mn = fmaxf(mmax, sc);
    float scale = __expf(mmax - mn);
    float p = __expf(sc - mn);
    l = l*scale + p;
    #pragma unroll
    for (int d = 0; d < Dc; d++) acc[d] = fmaf(p, vs[j][d], acc[d]*scale);
    mmax = mn;
  }
  float inv = 1.f / l;
  float* obase = g_att + (size_t)(b*Sc + i)*E2c + hh*Dc;
  #pragma unroll
  for (int d = 0; d < Dc; d++) obase[d] = acc[d] * inv;
}

// ---------------- residual + LN + gelu (+ fp16 fused) ------------------------
__global__ void k_res_ln_gelu(const float* __restrict__ ls, const float* __restrict__ lo) {
  int row = blockIdx.x; int e = threadIdx.x;
  int idx = row*E2c + e;
  float v = g_h[idx] + g_att[idx];
  float s1 = v, s2 = v*v;
  blk_reduce2(s1, s2);
  float mu = s1 * (1.f/E2c);
  float var = s2 * (1.f/E2c) - mu*mu;
  float y = gelu_f((v - mu) * rsqrtf(var + 1e-5f) * ls[e] + lo[e]);
  g_h[idx] = y;
  g_Fh[idx] = __float2half_rn(y);
}

// ---------------- fc GEMM: A via single bulk-copy, W via cp.async ------------
#define FC_BN 48
#define FC_IT (FLATc/32)        // 384
#define FC_ST 4
#define FC_ABYTES 8192
#define FC_WBYTES 6144
#define FST_SZ (FC_ABYTES + FC_WBYTES)   // 14336
#define FMB_OFF 0
#define FSTG_OFF 64
#define FCV_OFF (FSTG_OFF + FC_ST*FST_SZ)  // 57408
#define FW_PAD 112
#define FC_SMEM (FCV_OFF + 32*FW_PAD)      // 60992

__global__ void __launch_bounds__(256, 2) k_fc_mma(const float* __restrict__ W,
                                                   const float* __restrict__ bias) {
  extern __shared__ char smc[];
  uint32_t sb = smem_u32(smc);
  int tid = threadIdx.x, lane = tid & 31, wp = tid >> 5;
  int warpM = wp >> 1, warpN = wp & 1;
  int n0 = blockIdx.x * FC_BN;

  float acc[2][3][4];
  #pragma unroll
  for (int i = 0; i < 2; i++)
    #pragma unroll
    for (int j = 0; j < 3; j++)
      #pragma unroll
      for (int c = 0; c < 4; c++) acc[i][j][c] = 0.f;

  if (tid == 0) {
    #pragma unroll
    for (int s = 0; s < FC_ST; s++)
      asm volatile("mbarrier.init.shared.b64 [%0], 1;" :: "r"(sb + FMB_OFF + s*8) : "memory");
  }
  __syncthreads();

  auto issue_W = [&](int slot, int kit) {
    uint32_t st = sb + FSTG_OFF + slot*FST_SZ + FC_ABYTES;
    {
      int k = tid / 12, c = tid % 12;
      cp16(st + k*192 + c*16, W + (size_t)(kit*32 + k)*FLATc + n0 + c*4);
    }
    if (tid < 128) {
      int g2 = tid + 256;
      int k = g2 / 12, c = g2 % 12;
      cp16(st + k*192 + c*16, W + (size_t)(kit*32 + k)*FLATc + n0 + c*4);
    }
  };
  auto issue_A = [&](int slot, int kit) {
    uint32_t st = sb + FSTG_OFF + slot*FST_SZ;
    uint32_t mb = sb + FMB_OFF + slot*8;
    if (lane == 0) {
      asm volatile("mbarrier.arrive.expect_tx.shared.b64 _, [%0], %1;"
                   :: "r"(mb), "r"((uint32_t)FC_ABYTES) : "memory");
      bulkcp(st, (const char*)g_Ft + (size_t)kit*FC_ABYTES, FC_ABYTES, mb);
    }
  };

  #pragma unroll
  for (int s = 0; s < FC_ST - 1; s++) {
    issue_W(s, s);
    asm volatile("cp.async.commit_group;" ::: "memory");
    if (wp == 0) issue_A(s, s);
  }

  uint32_t phbits = 0;
  int arow = warpM*32 + (lane & 15);
  int ckrow = tid >> 3, cseg = tid & 7;

  for (int it = 0; it < FC_IT; it++) {
    int slot = it & 3;
    asm volatile("cp.async.wait_group 2;" ::: "memory");
    mbar_wait_acq(sb + FMB_OFF + slot*8, (phbits >> slot) & 1);
    phbits ^= 1u << slot;
    __syncthreads();

    if (it + FC_ST - 1 < FC_IT) issue_W((it + FC_ST - 1) & 3, it + FC_ST - 1);
    asm volatile("cp.async.commit_group;" ::: "memory");
    if (wp == 0 && it + FC_ST - 1 < FC_IT) issue_A((it + FC_ST - 1) & 3, it + FC_ST - 1);

    {
      uint32_t src = sb + FSTG_OFF + slot*FST_SZ + FC_ABYTES + (uint32_t)ckrow*192 + cseg*24;
      uint32_t dh  = sb + FCV_OFF + (uint32_t)ckrow*FW_PAD + cseg*12;
      float2 f0, f1, f2;
      asm volatile("ld.shared.v2.f32 {%0,%1}, [%2];" : "=f"(f0.x), "=f"(f0.y) : "r"(src));
      asm volatile("ld.shared.v2.f32 {%0,%1}, [%2];" : "=f"(f1.x), "=f"(f1.y) : "r"(src + 8));
      asm volatile("ld.shared.v2.f32 {%0,%1}, [%2];" : "=f"(f2.x), "=f"(f2.y) : "r"(src + 16));
      uint32_t h0 = pack2h(f0.x, f0.y), h1 = pack2h(f1.x, f1.y), h2 = pack2h(f2.x, f2.y);
      asm volatile("st.shared.b32 [%0], %1;" :: "r"(dh),     "r"(h0));
      asm volatile("st.shared.b32 [%0], %1;" :: "r"(dh + 4), "r"(h1));
      asm volatile("st.shared.b32 [%0], %1;" :: "r"(dh + 8), "r"(h2));
    }
    __syncthreads();

    uint32_t st = sb + FSTG_OFF + slot*FST_SZ;
    uint32_t cv = sb + FCV_OFF;
    #pragma unroll
    for (int ks = 0; ks < 2; ks++) {
      uint4 fah[2];
      int c = ks*2 + (lane >> 4);
      #pragma unroll
      for (int i = 0; i < 2; i++) {
        int row = arow + i*16;
        uint32_t sw = (uint32_t)((c ^ ((row >> 1) & 3)) * 16);
        uint32_t ad = st + (uint32_t)row*64 + sw;
        asm volatile("ldmatrix.sync.aligned.m8n8.x4.shared.b16 {%0,%1,%2,%3}, [%4];"
          : "=r"(fah[i].x), "=r"(fah[i].y), "=r"(fah[i].z), "=r"(fah[i].w) : "r"(ad));
      }
      uint2 fwh[3];
      int kl = ks*16 + (lane & 15);
      #pragma unroll
      for (int j = 0; j < 3; j++) {
        uint32_t wd = cv + (uint32_t)kl*FW_PAD + (uint32_t)(warpN*24 + j*8)*2;
        asm volatile("ldmatrix.sync.aligned.m8n8.x2.trans.shared.b16 {%0,%1}, [%2];"
          : "=r"(fwh[j].x), "=r"(fwh[j].y) : "r"(wd));
      }
      #pragma unroll
      for (int i = 0; i < 2; i++)
        #pragma unroll
        for (int j = 0; j < 3; j++) MMAH16816(acc[i][j], fah[i], fwh[j]);
    }
  }

  int g = lane >> 2, q = lane & 3;
  #pragma unroll
  for (int i = 0; i < 2; i++) {
    int m = warpM*32 + i*16 + g;
    #pragma unroll
    for (int j = 0; j < 3; j++) {
      int n = n0 + warpN*24 + j*8 + q*2;
      float b0 = bias[n], b1 = bias[n+1];
      float2 r0, r1;
      r0.x = gelu_f(acc[i][j][0] + b0);
      r0.y = gelu_f(acc[i][j][1] + b1);
      r1.x = gelu_f(acc[i][j][2] + b0);
      r1.y = gelu_f(acc[i][j][3] + b1);
      *(float2*)(g_f + (size_t)m*FLATc + n)       = r0;
      *(float2*)(g_f + (size_t)(m + 8)*FLATc + n) = r1;
    }
  }
}

// ---------------- LN over FLAT -----------------------------------------------
__global__ void k_ln_flat(const float* __restrict__ ls, const float* __restrict__ lo) {
  int b = blockIdx.x; int t = threadIdx.x;
  float* frow = g_f + (size_t)b*FLATc;
  float s1 = 0.f, s2 = 0.f;
  for (int k = t; k < FLATc; k += 256) { float v = frow[k]; s1 += v; s2 += v*v; }
  blk_reduce2(s1, s2);
  float mu = s1 * (1.f/FLATc);
  float var = s2 * (1.f/FLATc) - mu*mu;
  float rs = rsqrtf(var + 1e-5f);
  for (int k = t; k < FLATc; k += 256) {
    float v = frow[k];
    frow[k] = (v - mu) * rs * ls[k] + lo[k];
  }
}

// ---------------- final out GEMM ---------------------------------------------
__global__ void k_out(const float* __restrict__ ow, const float* __restrict__ ob,
                      float* __restrict__ out) {
  int o = blockIdx.x, b = blockIdx.y;
  int t = threadIdx.x;
  const float* frow = g_f + (size_t)b*FLATc;
  float s1 = 0.f, s2 = 0.f;
  for (int k = t; k < FLATc; k += 256) s1 = fmaf(frow[k], ow[(size_t)k*HORc + o], s1);
  blk_reduce2(s1, s2);
  if (t == 0) out[b*HORc + o] = s1 + ob[o];
}

// ---------------- launch ------------------------------------------------------
extern "C" void kernel_launch(void* const* d_in, const int* in_sizes, int n_in,
                              void* d_out, int out_size) {
  const float* x      = (const float*)d_in[0];
  const float* proj_w = (const float*)d_in[1];
  const float* proj_b = (const float*)d_in[2];
  const float* ln0_s  = (const float*)d_in[3];
  const float* ln0_o  = (const float*)d_in[4];
  const float* conv_w = (const float*)d_in[5];
  const float* conv_b = (const float*)d_in[6];
  const float* ln1_s  = (const float*)d_in[7];
  const float* ln1_o  = (const float*)d_in[8];
  const float* qk_w   = (const float*)d_in[9];
  const float* qk_b   = (const float*)d_in[10];
  const float* mass_w = (const float*)d_in[11];
  const float* mass_b = (const float*)d_in[12];
  const float* v_w    = (const float*)d_in[13];
  const float* v_b    = (const float*)d_in[14];
  const float* norm_s = (const float*)d_in[15];
  const float* norm_o = (const float*)d_in[16];
  const float* mlp_w1 = (const float*)d_in[17];
  const float* mlp_b1 = (const float*)d_in[18];
  const float* mlp_w2 = (const float*)d_in[19];
  const float* mlp_b2 = (const float*)d_in[20];
  const float* fc_w   = (const float*)d_in[21];
  const float* fc_b   = (const float*)d_in[22];
  const float* ln2_s  = (const float*)d_in[23];
  const float* ln2_o  = (const float*)d_in[24];
  const float* out_w  = (const float*)d_in[25];
  const float* out_b  = (const float*)d_in[26];

  float *p_h, *p_qk, *p_v, *p_conv;
  __half *p_F0, *p_Fh, *p_FMh, *p_Ft;
  cudaGetSymbolAddress((void**)&p_h,    g_h);
  cudaGetSymbolAddress((void**)&p_qk,   g_qk);
  cudaGetSymbolAddress((void**)&p_v,    g_v);
  cudaGetSymbolAddress((void**)&p_conv, g_conv);
  cudaGetSymbolAddress((void**)&p_F0,   g_F0);
  cudaGetSymbolAddress((void**)&p_Fh,   g_Fh);
  cudaGetSymbolAddress((void**)&p_FMh,  g_FMh);
  cudaGetSymbolAddress((void**)&p_Ft,   g_Ft);

  cudaFuncSetAttribute(k_fc_mma, cudaFuncAttributeMaxDynamicSharedMemorySize, FC_SMEM);
  cudaFuncSetAttribute(k_gemm_tc, cudaFuncAttributeMaxDynamicSharedMemorySize, GT_SMEM);
  cudaFuncSetAttribute(k_conv_tc, cudaFuncAttributeMaxDynamicSharedMemorySize, GT_SMEM);

  k_proj<<<ROWS, Ec>>>(x, proj_w, proj_b, ln0_s, ln0_o);
  k_conv_tc<<<dim3(E2c/64, ROWS/128), 256, GT_SMEM>>>(p_F0, conv_w, conv_b, p_conv);
  k_ln_gelu_conv<<<ROWS, E2c>>>(ln1_s, ln1_o);

  for (int l = 0; l < Lc; l++) {
    k_gemm_tc<<<dim3(E2c/64, ROWS/128, 2), 256, GT_SMEM>>>(
        p_Fh, qk_w + (size_t)l*E2c*E2c, qk_b + l*E2c,
        nullptr, p_qk, nullptr, nullptr,
        v_w + (size_t)l*E2c*E2c, v_b + l*E2c, p_v,
        E2c, E2c, 0);
    k_mass<<<ROWS/32, 256>>>(mass_w + (size_t)l*E2c*Hc, mass_b + l*Hc);
    k_attn<<<Bc*Hc, Sc>>>();
    k_res_ln_gelu<<<ROWS, E2c>>>(norm_s + l*E2c, norm_o + l*E2c);
  }

  k_gemm_tc<<<dim3(MLPH/64, ROWS/128, 1), 256, GT_SMEM>>>(
      p_Fh, mlp_w1, mlp_b1, nullptr, nullptr, p_FMh, nullptr,
      nullptr, nullptr, nullptr, MLPH, E2c, 1);
  k_gemm_tc<<<dim3(E2c/64, ROWS/128, 1), 256, GT_SMEM>>>(
      p_FMh, mlp_w2, mlp_b2, p_h, p_h, nullptr, p_Ft,
      nullptr, nullptr, nullptr, E2c, MLPH, 2);

  k_fc_mma<<<FLATc/FC_BN, 256, FC_SMEM>>>(fc_w, fc_b);
  k_ln_flat<<<Bc, 256>>>(ln2_s, ln2_o);
  k_out<<<dim3(HORc, Bc), 256>>>(out_w, out_b, (float*)d_out);
}